// round 2
// baseline (speedup 1.0000x reference)
#include <cuda_runtime.h>
#include <math.h>

// Problem constants
#define NIMG 8
#define CCH  3
#define HI   512
#define WI   512
#define HO   2048
#define WO   2048

// Per-layer affine params: a, tx, b, ty (matching reference formulas exactly)
__device__ float4 g_prm[NIMG];

__device__ __forceinline__ float sigm(float z) {
    return 1.0f / (1.0f + expf(-z));
}

__global__ void prm_kernel(const float* __restrict__ coor) {
    int n = threadIdx.x;
    if (n < NIMG) {
        float x = sigm(coor[4 * n + 0]) * (float)WO;
        float y = sigm(coor[4 * n + 1]) * (float)HO;
        float w = sigm(coor[4 * n + 2]) * (float)WO;
        float h = sigm(coor[4 * n + 3]) * (float)HO;
        float a  = (float)WO / (w + 1e-8f);
        float tx = (2.0f / (float)WO) * ((float)WO * 0.5f - x) * a;
        float b  = (float)HO / (h + 1e-8f);
        float ty = (2.0f / (float)HO) * ((float)HO * 0.5f - y) * b;
        g_prm[n] = make_float4(a, tx, b, ty);
    }
}

// One thread handles 4 consecutive x pixels (float4 per channel).
// blockDim = (32, 8): warp covers 128 contiguous px in one row.
__global__ __launch_bounds__(256) void composite_kernel(
    const float* __restrict__ src,   // [8,3,512,512]
    const float* __restrict__ bg,    // [1,3,2048,2048]
    float* __restrict__ out)         // [1,3,2048,2048]
{
    const int px0 = (blockIdx.x * blockDim.x + threadIdx.x) * 4;
    const int py  = blockIdx.y * blockDim.y + threadIdx.y;
    const int HW  = HO * WO;
    const int base = py * WO + px0;

    // Load background (3 channels x 4 px)
    float4 a0 = *reinterpret_cast<const float4*>(bg + base);
    float4 a1 = *reinterpret_cast<const float4*>(bg + HW + base);
    float4 a2 = *reinterpret_cast<const float4*>(bg + 2 * HW + base);
    float acc[3][4] = {
        {a0.x, a0.y, a0.z, a0.w},
        {a1.x, a1.y, a1.z, a1.w},
        {a2.x, a2.y, a2.z, a2.w}
    };

    const float ys = (float)(2 * py + 1) * (1.0f / (float)HO) - 1.0f;

#pragma unroll
    for (int n = 0; n < NIMG; n++) {
        const float4 p = g_prm[n];   // a, tx, b, ty

        // y source coordinate (grid_sample unnormalize, align_corners=False)
        const float gy = p.z * ys + p.w;
        const float iy = ((gy + 1.0f) * (float)HI - 1.0f) * 0.5f;
        if (iy <= -1.0f || iy >= (float)HI) continue;

        // group x-range reject (Ax > 0, monotone in px)
        const float xsA = (float)(2 * px0 + 1)     * (1.0f / (float)WO) - 1.0f;
        const float xsB = (float)(2 * (px0+3) + 1) * (1.0f / (float)WO) - 1.0f;
        const float ixA = ((p.x * xsA + p.y + 1.0f) * (float)WI - 1.0f) * 0.5f;
        const float ixB = ((p.x * xsB + p.y + 1.0f) * (float)WI - 1.0f) * 0.5f;
        if (ixB <= -1.0f || ixA >= (float)WI) continue;

        // y weights + validity (zeros padding semantics)
        const float y0f = floorf(iy);
        const float wy1 = iy - y0f;
        const float wy0 = 1.0f - wy1;
        const int   y0  = (int)y0f;
        const int   y1  = y0 + 1;
        const float wyv0 = (y0 >= 0 && y0 < HI) ? wy0 : 0.0f;
        const float wyv1 = (y1 >= 0 && y1 < HI) ? wy1 : 0.0f;
        const int y0c = min(max(y0, 0), HI - 1);
        const int y1c = min(max(y1, 0), HI - 1);
        const float my = wyv0 + wyv1;

        const float* sbase = src + (size_t)n * CCH * HI * WI;
        const float* r0 = sbase + y0c * WI;   // + c*HI*WI per channel
        const float* r1 = sbase + y1c * WI;

#pragma unroll
        for (int j = 0; j < 4; j++) {
            const int px = px0 + j;
            const float xs = (float)(2 * px + 1) * (1.0f / (float)WO) - 1.0f;
            const float gx = p.x * xs + p.y;
            const float ix = ((gx + 1.0f) * (float)WI - 1.0f) * 0.5f;

            const float x0f = floorf(ix);
            const float wx1 = ix - x0f;
            const float wx0 = 1.0f - wx1;
            const int   x0  = (int)x0f;
            const int   x1  = x0 + 1;
            const float wxv0 = (x0 >= 0 && x0 < WI) ? wx0 : 0.0f;
            const float wxv1 = (x1 >= 0 && x1 < WI) ? wx1 : 0.0f;
            const int x0c = min(max(x0, 0), WI - 1);
            const int x1c = min(max(x1, 0), WI - 1);

            const float m  = my * (wxv0 + wxv1);
            if (m == 0.0f) continue;
            const float km = 1.0f - m;

#pragma unroll
            for (int c = 0; c < CCH; c++) {
                const float* rc0 = r0 + c * (HI * WI);
                const float* rc1 = r1 + c * (HI * WI);
                const float v00 = __ldg(rc0 + x0c);
                const float v10 = __ldg(rc1 + x0c);
                const float v01 = __ldg(rc0 + x1c);
                const float v11 = __ldg(rc1 + x1c);
                const float rowA = v00 * wyv0 + v10 * wyv1;  // rows at x0c
                const float rowB = v01 * wyv0 + v11 * wyv1;  // rows at x1c
                const float s = rowA * wxv0 + rowB * wxv1;   // bilinear sample
                acc[c][j] = acc[c][j] * km + s * m;
            }
        }
    }

    *reinterpret_cast<float4*>(out + base) =
        make_float4(acc[0][0], acc[0][1], acc[0][2], acc[0][3]);
    *reinterpret_cast<float4*>(out + HW + base) =
        make_float4(acc[1][0], acc[1][1], acc[1][2], acc[1][3]);
    *reinterpret_cast<float4*>(out + 2 * HW + base) =
        make_float4(acc[2][0], acc[2][1], acc[2][2], acc[2][3]);
}

extern "C" void kernel_launch(void* const* d_in, const int* in_sizes, int n_in,
                              void* d_out, int out_size) {
    const float* src  = (const float*)d_in[0];  // [8,3,512,512]
    const float* bg   = (const float*)d_in[1];  // [1,3,2048,2048]
    const float* coor = (const float*)d_in[2];  // [8,4]
    float* out = (float*)d_out;                 // [1,3,2048,2048]

    prm_kernel<<<1, 32>>>(coor);

    dim3 block(32, 8);
    dim3 grid(WO / (4 * 32), HO / 8);   // (16, 256)
    composite_kernel<<<grid, block>>>(src, bg, out);
}

// round 3
// speedup vs baseline: 1.6473x; 1.6473x over previous
#include <cuda_runtime.h>
#include <math.h>

// Problem constants
#define NIMG 8
#define CCH  3
#define HI   512
#define WI   512
#define HO   2048
#define WO   2048

// Per-layer affine params: a, tx, b, ty (matching reference formulas exactly)
__device__ float4 g_prm[NIMG];

__device__ __forceinline__ float sigm(float z) {
    return 1.0f / (1.0f + expf(-z));
}

__global__ void prm_kernel(const float* __restrict__ coor) {
    int n = threadIdx.x;
    if (n < NIMG) {
        float x = sigm(coor[4 * n + 0]) * (float)WO;
        float y = sigm(coor[4 * n + 1]) * (float)HO;
        float w = sigm(coor[4 * n + 2]) * (float)WO;
        float h = sigm(coor[4 * n + 3]) * (float)HO;
        float a  = (float)WO / (w + 1e-8f);
        float tx = (2.0f / (float)WO) * ((float)WO * 0.5f - x) * a;
        float b  = (float)HO / (h + 1e-8f);
        float ty = (2.0f / (float)HO) * ((float)HO * 0.5f - y) * b;
        g_prm[n] = make_float4(a, tx, b, ty);
    }
}

// Back-to-front compositing with early termination:
//   out = sum_n s_n*m_n*prod_{k>n}(1-m_k) + bg*prod(1-m)
// A layer whose box fully covers a pixel has m == 1 (to ~1e-7), so once a
// thread hits a fully-interior layer its transparency T goes to 0 and it can
// stop (skipping all earlier layers AND the bg load).
// One thread = 4 consecutive x pixels (float4 bg/out per channel).
__global__ __launch_bounds__(256) void composite_kernel(
    const float* __restrict__ src,   // [8,3,512,512]
    const float* __restrict__ bg,    // [1,3,2048,2048]
    float* __restrict__ out)         // [1,3,2048,2048]
{
    const int px0 = (blockIdx.x * blockDim.x + threadIdx.x) * 4;
    const int py  = blockIdx.y * blockDim.y + threadIdx.y;
    const int HW  = HO * WO;
    const int base = py * WO + px0;

    float A[3][4] = {{0.f,0.f,0.f,0.f},{0.f,0.f,0.f,0.f},{0.f,0.f,0.f,0.f}};
    float T[4] = {1.f, 1.f, 1.f, 1.f};

    const float ys  = (float)(2 * py + 1) * (1.0f / (float)HO) - 1.0f;
    const float xsA = (float)(2 * px0 + 1)       * (1.0f / (float)WO) - 1.0f;
    const float xsB = (float)(2 * (px0 + 3) + 1) * (1.0f / (float)WO) - 1.0f;

#pragma unroll
    for (int n = NIMG - 1; n >= 0; n--) {
        const float4 p = g_prm[n];   // a, tx, b, ty

        // y source coordinate (grid_sample unnormalize, align_corners=False)
        const float gy = p.z * ys + p.w;
        const float iy = ((gy + 1.0f) * (float)HI - 1.0f) * 0.5f;
        if (iy <= -1.0f || iy >= (float)HI) continue;

        // group x-range reject (a > 0, ix monotone in px)
        const float ixA = ((p.x * xsA + p.y + 1.0f) * (float)WI - 1.0f) * 0.5f;
        const float ixB = ((p.x * xsB + p.y + 1.0f) * (float)WI - 1.0f) * 0.5f;
        if (ixB <= -1.0f || ixA >= (float)WI) continue;

        const float y0f = floorf(iy);
        const float wy1 = iy - y0f;
        const float wy0 = 1.0f - wy1;
        const int   y0  = (int)y0f;
        const int   y1  = y0 + 1;
        const float* sbase = src + (size_t)n * CCH * HI * WI;

        const bool interior = (iy >= 0.0f) && (iy < (float)(HI - 1)) &&
                              (ixA >= 0.0f) && (ixB < (float)(WI - 1));

        if (interior) {
            // m == 1 for all 4 px: sample overwrites everything below.
            const float* r0 = sbase + y0 * WI;
            const float* r1 = r0 + WI;
#pragma unroll
            for (int j = 0; j < 4; j++) {
                const int px = px0 + j;
                const float xs = (float)(2 * px + 1) * (1.0f / (float)WO) - 1.0f;
                const float gx = p.x * xs + p.y;
                const float ix = ((gx + 1.0f) * (float)WI - 1.0f) * 0.5f;
                const float x0f = floorf(ix);
                const float wx1 = ix - x0f;
                const float wx0 = 1.0f - wx1;
                const int   x0  = (int)x0f;
#pragma unroll
                for (int c = 0; c < CCH; c++) {
                    const float* rc0 = r0 + c * (HI * WI);
                    const float* rc1 = r1 + c * (HI * WI);
                    const float v00 = __ldg(rc0 + x0);
                    const float v10 = __ldg(rc1 + x0);
                    const float v01 = __ldg(rc0 + x0 + 1);
                    const float v11 = __ldg(rc1 + x0 + 1);
                    const float rowA = v00 * wy0 + v10 * wy1;
                    const float rowB = v01 * wy0 + v11 * wy1;
                    const float s = rowA * wx0 + rowB * wx1;
                    A[c][j] = fmaf(T[j], s, A[c][j]);
                }
                T[j] = 0.0f;
            }
            break;   // all 4 px fully opaque: earlier layers + bg invisible
        } else {
            // Boundary path: full reference semantics (validity + clamps).
            const float wyv0 = (y0 >= 0 && y0 < HI) ? wy0 : 0.0f;
            const float wyv1 = (y1 >= 0 && y1 < HI) ? wy1 : 0.0f;
            const int y0c = min(max(y0, 0), HI - 1);
            const int y1c = min(max(y1, 0), HI - 1);
            const float my = wyv0 + wyv1;
            const float* r0 = sbase + y0c * WI;
            const float* r1 = sbase + y1c * WI;
#pragma unroll
            for (int j = 0; j < 4; j++) {
                const int px = px0 + j;
                const float xs = (float)(2 * px + 1) * (1.0f / (float)WO) - 1.0f;
                const float gx = p.x * xs + p.y;
                const float ix = ((gx + 1.0f) * (float)WI - 1.0f) * 0.5f;

                const float x0f = floorf(ix);
                const float wx1 = ix - x0f;
                const float wx0 = 1.0f - wx1;
                const int   x0  = (int)x0f;
                const int   x1  = x0 + 1;
                const float wxv0 = (x0 >= 0 && x0 < WI) ? wx0 : 0.0f;
                const float wxv1 = (x1 >= 0 && x1 < WI) ? wx1 : 0.0f;
                const int x0c = min(max(x0, 0), WI - 1);
                const int x1c = min(max(x1, 0), WI - 1);

                const float m = my * (wxv0 + wxv1);
                if (m == 0.0f) continue;
                const float wgt = T[j] * m;
#pragma unroll
                for (int c = 0; c < CCH; c++) {
                    const float* rc0 = r0 + c * (HI * WI);
                    const float* rc1 = r1 + c * (HI * WI);
                    const float v00 = __ldg(rc0 + x0c);
                    const float v10 = __ldg(rc1 + x0c);
                    const float v01 = __ldg(rc0 + x1c);
                    const float v11 = __ldg(rc1 + x1c);
                    const float rowA = v00 * wyv0 + v10 * wyv1;
                    const float rowB = v01 * wyv0 + v11 * wyv1;
                    const float s = rowA * wxv0 + rowB * wxv1;
                    A[c][j] = fmaf(wgt, s, A[c][j]);
                }
                T[j] *= (1.0f - m);
            }
        }
    }

    // Background contribution only where transparency survives.
    const float Tm = fmaxf(fmaxf(T[0], T[1]), fmaxf(T[2], T[3]));
    if (Tm > 0.0f) {
        const float4 b0 = *reinterpret_cast<const float4*>(bg + base);
        const float4 b1 = *reinterpret_cast<const float4*>(bg + HW + base);
        const float4 b2 = *reinterpret_cast<const float4*>(bg + 2 * HW + base);
        A[0][0] = fmaf(b0.x, T[0], A[0][0]);
        A[0][1] = fmaf(b0.y, T[1], A[0][1]);
        A[0][2] = fmaf(b0.z, T[2], A[0][2]);
        A[0][3] = fmaf(b0.w, T[3], A[0][3]);
        A[1][0] = fmaf(b1.x, T[0], A[1][0]);
        A[1][1] = fmaf(b1.y, T[1], A[1][1]);
        A[1][2] = fmaf(b1.z, T[2], A[1][2]);
        A[1][3] = fmaf(b1.w, T[3], A[1][3]);
        A[2][0] = fmaf(b2.x, T[0], A[2][0]);
        A[2][1] = fmaf(b2.y, T[1], A[2][1]);
        A[2][2] = fmaf(b2.z, T[2], A[2][2]);
        A[2][3] = fmaf(b2.w, T[3], A[2][3]);
    }

    *reinterpret_cast<float4*>(out + base) =
        make_float4(A[0][0], A[0][1], A[0][2], A[0][3]);
    *reinterpret_cast<float4*>(out + HW + base) =
        make_float4(A[1][0], A[1][1], A[1][2], A[1][3]);
    *reinterpret_cast<float4*>(out + 2 * HW + base) =
        make_float4(A[2][0], A[2][1], A[2][2], A[2][3]);
}

extern "C" void kernel_launch(void* const* d_in, const int* in_sizes, int n_in,
                              void* d_out, int out_size) {
    const float* src  = (const float*)d_in[0];  // [8,3,512,512]
    const float* bg   = (const float*)d_in[1];  // [1,3,2048,2048]
    const float* coor = (const float*)d_in[2];  // [8,4]
    float* out = (float*)d_out;                 // [1,3,2048,2048]

    prm_kernel<<<1, 32>>>(coor);

    dim3 block(32, 8);
    dim3 grid(WO / (4 * 32), HO / 8);   // (16, 256)
    composite_kernel<<<grid, block>>>(src, bg, out);
}